// round 14
// baseline (speedup 1.0000x reference)
#include <cuda_runtime.h>
#include <cuda_bf16.h>
#include <math.h>
#include <stdint.h>

#define B_ 128
#define L_ 128
#define T_ (B_*L_)
#define DIN_ 6
#define D_ 256
#define H_ 8
#define DK_ 32
#define NL_ 6
#define NE_ 8
#define NMOE_ 3
#define DFF_ 1024
#define NOUT_ 5

// ---------------- device scratch (no allocations allowed) ----------------
__device__ float g_h[T_*D_];                         // fp32 residual stream
__device__ __nv_bfloat16 g_hx[T_*D_];                // bf16 mirror of g_h
__device__ __nv_bfloat16 g_qx[T_*D_];
__device__ __nv_bfloat16 g_kx[T_*D_];
__device__ __nv_bfloat16 g_vx[T_*D_];
__device__ __nv_bfloat16 g_aox[T_*D_];               // attention output (bf16)
__device__ float g_eo[(size_t)NE_*T_*D_];            // expert outputs (fp32)
__device__ __nv_bfloat16 g_hb[(size_t)NE_*T_*DFF_];  // FFN hidden (bf16)
__device__ int   g_cnt[NE_];
__device__ int   g_list[NE_*T_];
__device__ int   g_ebuf[T_*2];
__device__ int   g_pbuf[T_*2];
__device__ float g_wbuf[T_*2];
// pre-transposed bf16 weights, K-major [n][k]
__device__ __nv_bfloat16 g_wta[NL_*4*D_*D_];               // [layer][q,k,v,o][n][k]
__device__ __nv_bfloat16 g_w1t[(size_t)NMOE_*NE_*DFF_*D_]; // [m][e][dff][d]
__device__ __nv_bfloat16 g_w2t[(size_t)NMOE_*NE_*D_*DFF_]; // [m][e][d][dff]

__device__ __forceinline__ uint32_t smem_u32(const void* p) {
    uint32_t a;
    asm("{ .reg .u64 t; cvta.to.shared.u64 t, %1; cvt.u32.u64 %0, t; }" : "=r"(a) : "l"(p));
    return a;
}

// ---------------- weight transpose: fp32 [K][N] -> bf16 [N][K] ----------------
__global__ void transpose_w(const float* __restrict__ src, __nv_bfloat16* __restrict__ dst,
                            int K, int N, size_t srcStride, size_t dstOff, size_t dstStride) {
    __shared__ float tile[32][33];
    int z = blockIdx.z;
    const float* sm_ = src + (size_t)z*srcStride;
    __nv_bfloat16* dm = dst + dstOff + (size_t)z*dstStride;
    int k0 = blockIdx.x*32, n0 = blockIdx.y*32;
    int tid = threadIdx.x;
#pragma unroll
    for (int i = 0; i < 4; i++) {
        int f = tid + i*256;
        int kk = f >> 5, nn = f & 31;
        tile[kk][nn] = sm_[(size_t)(k0 + kk)*N + n0 + nn];
    }
    __syncthreads();
#pragma unroll
    for (int i = 0; i < 2; i++) {
        int f = tid + i*256;
        int r = f >> 4, c = f & 15;
        __nv_bfloat162 v = __floats2bfloat162_rn(tile[2*c][r], tile[2*c + 1][r]);
        *(__nv_bfloat162*)(dm + (size_t)(n0 + r)*K + k0 + 2*c) = v;
    }
}

// fused attention-weight transpose: z = layer*4 + {q,k,v,o}
__global__ void transpose_attnw(const float* __restrict__ wq, const float* __restrict__ wk,
                                const float* __restrict__ wv, const float* __restrict__ wo,
                                __nv_bfloat16* __restrict__ dst) {
    __shared__ float tile[32][33];
    int z = blockIdx.z;
    int layer = z >> 2, widx = z & 3;
    const float* srcs[4] = {wq, wk, wv, wo};
    const float* sm_ = srcs[widx] + (size_t)layer*D_*D_;
    __nv_bfloat16* dm = dst + (size_t)z*D_*D_;
    int k0 = blockIdx.x*32, n0 = blockIdx.y*32;
    int tid = threadIdx.x;
#pragma unroll
    for (int i = 0; i < 4; i++) {
        int f = tid + i*256;
        int kk = f >> 5, nn = f & 31;
        tile[kk][nn] = sm_[(size_t)(k0 + kk)*D_ + n0 + nn];
    }
    __syncthreads();
#pragma unroll
    for (int i = 0; i < 2; i++) {
        int f = tid + i*256;
        int r = f >> 4, c = f & 15;
        __nv_bfloat162 v = __floats2bfloat162_rn(tile[2*c][r], tile[2*c + 1][r]);
        *(__nv_bfloat162*)(dm + (size_t)(n0 + r)*D_ + k0 + 2*c) = v;
    }
}

// ---------------- embed: 128 tokens/block, x staged in smem, w in registers --------
__global__ void embed_kernel(const float* __restrict__ x,
                             const float* __restrict__ w,
                             const float* __restrict__ b) {
    __shared__ float xs[128*DIN_];
    int d = threadIdx.x;
    int t0 = blockIdx.x * 128;
    if (blockIdx.x == 0 && d < NE_) g_cnt[d] = 0;     // zero MoE counters for layer 0
#pragma unroll
    for (int i = 0; i < 3; i++) xs[d + i*256] = x[(size_t)t0*DIN_ + d + i*256];
    float wr[DIN_];
#pragma unroll
    for (int i = 0; i < DIN_; i++) wr[i] = w[i*D_ + d];
    float bb = b[d];
    __syncthreads();
#pragma unroll 4
    for (int tk = 0; tk < 128; tk++) {
        float acc = bb;
#pragma unroll
        for (int i = 0; i < DIN_; i++) acc += xs[tk*DIN_ + i] * wr[i];
        g_h[(size_t)(t0 + tk)*D_ + d] = acc;
        g_hx[(size_t)(t0 + tk)*D_ + d] = __float2bfloat16(acc);
    }
}

// ---------------- bf16 tensor-core GEMM, 3-stage cp.async (16B), 1 barrier/chunk ----
#define EPI_NONE      0
#define EPI_RES       1
#define EPI_BIAS_GELU 2
#define EPI_BIAS      3

#define KROW 20
#define STG_U32 (128*KROW)                 // 2560 u32 = 10240 B per operand stage
#define GEMM_SMEM (6*STG_U32*4)            // 61440 B (A0..A2, B0..B2)

template<int EPI>
__global__ __launch_bounds__(256, 2)
void bf_gemm(const __nv_bfloat16* __restrict__ A, int lda, size_t strideA,
             const __nv_bfloat16* __restrict__ Wt, size_t strideW,
             float* __restrict__ C, __nv_bfloat16* __restrict__ Cb,
             __nv_bfloat16* __restrict__ Cb2, __nv_bfloat16* __restrict__ Cb3,
             int ldc, size_t strideC,
             __nv_bfloat16* __restrict__ mirror, size_t strideMir,
             const float* __restrict__ bias, size_t strideBias,
             const float* __restrict__ res,
             const int* __restrict__ gather, size_t strideGather,
             const int* __restrict__ cntPtr,
             int M, int N, int K, int qkv) {
    extern __shared__ float smf[];
    uint32_t smem_base = smem_u32(smf);

    int e = blockIdx.z;
    const __nv_bfloat16* Ae = A;
    const __nv_bfloat16* We = Wt + (size_t)e*strideW;
    float* Ce = nullptr;
    __nv_bfloat16* Cbe = nullptr;
    __nv_bfloat16* Me = nullptr;
    const float* be = nullptr;
    const int* ge = nullptr;
    int Mloc = M;
    if (qkv) {
        Cbe = (e == 0) ? Cb : (e == 1) ? Cb2 : Cb3;
    } else {
        Ae = A + (size_t)e*strideA;
        if (C) Ce = C + (size_t)e*strideC;
        if (mirror) Me = mirror + (size_t)e*strideMir;
        if (bias)   be = bias + (size_t)e*strideBias;
        if (gather) ge = gather + (size_t)e*strideGather;
        if (cntPtr) Mloc = cntPtr[e];
    }

    int bm = blockIdx.x * 128;
    if (bm >= Mloc) return;
    int bn = blockIdx.y * 128;

    int tid = threadIdx.x;
    int lane = tid & 31;
    int wid = tid >> 5;
    int wm = wid & 3;        // tok direction (4 x 32)
    int wn = wid >> 2;       // n direction  (2 x 64)

    // ---- per-thread cp.async descriptors: 16B ops, 2 per operand per thread ----
    const __nv_bfloat16* asrc[2]; int apred[2]; uint32_t adst[2];
    const __nv_bfloat16* bsrc[2]; uint32_t bdst[2];
#pragma unroll
    for (int p = 0; p < 2; p++) {
        int f = tid + p*256;
        int r = f >> 2, q = f & 3;               // row, 16B-chunk (8 bf16)
        int grow = bm + r;
        apred[p] = (grow < Mloc) ? 16 : 0;
        int gc = (grow < Mloc) ? grow : 0;
        int arow = ge ? ge[gc] : gc;
        asrc[p] = Ae + (size_t)arow*lda + q*8;
        adst[p] = (uint32_t)(r*KROW*4 + q*16);
        bsrc[p] = We + (size_t)(bn + r)*K + q*8;
        bdst[p] = (uint32_t)(r*KROW*4 + q*16);
    }

    auto load_chunk = [&](int st, int ki) {
        int k0 = ki << 5;
        uint32_t aBase = smem_base + (uint32_t)(st*STG_U32*4);
        uint32_t bBase = smem_base + (uint32_t)((3 + st)*STG_U32*4);
#pragma unroll
        for (int p = 0; p < 2; p++)
            asm volatile("cp.async.ca.shared.global [%0], [%1], 16, %2;"
                         :: "r"(aBase + adst[p]), "l"(asrc[p] + k0), "r"(apred[p]));
#pragma unroll
        for (int p = 0; p < 2; p++)
            asm volatile("cp.async.ca.shared.global [%0], [%1], 16;"
                         :: "r"(bBase + bdst[p]), "l"(bsrc[p] + k0));
        asm volatile("cp.async.commit_group;");
    };

    uint32_t aLdm = (uint32_t)(((wm*32 + (lane & 7) + 8*((lane >> 3) & 1))*KROW
                                + 4*(lane >> 4))*4);
    uint32_t bLdm = (uint32_t)(((wn*64 + (lane & 7) + 8*(lane >> 4))*KROW
                                + 4*((lane >> 3) & 1))*4);

    float acc[2][8][4];
#pragma unroll
    for (int mt = 0; mt < 2; mt++)
#pragma unroll
        for (int nt = 0; nt < 8; nt++)
#pragma unroll
            for (int i = 0; i < 4; i++) acc[mt][nt][i] = 0.f;

    int nk = K >> 5;
    load_chunk(0, 0);
    if (nk > 1) load_chunk(1, 1);

    int st = 0;
    for (int ki = 0; ki < nk; ki++) {
        if (ki + 1 < nk) asm volatile("cp.async.wait_group 1;");
        else             asm volatile("cp.async.wait_group 0;");
        __syncthreads();
        if (ki + 2 < nk) {
            int s2 = st + 2; if (s2 >= 3) s2 -= 3;
            load_chunk(s2, ki + 2);
        }

        uint32_t aB = smem_base + (uint32_t)(st*STG_U32*4) + aLdm;
        uint32_t bB = smem_base + (uint32_t)((3 + st)*STG_U32*4) + bLdm;
#pragma unroll
        for (int s = 0; s < 2; s++) {
            uint32_t aR[2][4];
#pragma unroll
            for (int mt = 0; mt < 2; mt++) {
                uint32_t addr = aB + (uint32_t)(mt*16*KROW*4 + s*32);
                asm volatile("ldmatrix.sync.aligned.m8n8.x4.shared.b16 {%0,%1,%2,%3}, [%4];"
                    : "=r"(aR[mt][0]), "=r"(aR[mt][1]), "=r"(aR[mt][2]), "=r"(aR[mt][3])
                    : "r"(addr));
            }
            uint32_t bR[4][4];
#pragma unroll
            for (int np = 0; np < 4; np++) {
                uint32_t addr = bB + (uint32_t)(np*16*KROW*4 + s*32);
                asm volatile("ldmatrix.sync.aligned.m8n8.x4.shared.b16 {%0,%1,%2,%3}, [%4];"
                    : "=r"(bR[np][0]), "=r"(bR[np][1]), "=r"(bR[np][2]), "=r"(bR[np][3])
                    : "r"(addr));
            }
#pragma unroll
            for (int mt = 0; mt < 2; mt++)
#pragma unroll
                for (int nt = 0; nt < 8; nt++) {
                    int np = nt >> 1, hi = nt & 1;
                    asm volatile(
                        "mma.sync.aligned.m16n8k16.row.col.f32.bf16.bf16.f32 "
                        "{%0,%1,%2,%3}, {%4,%5,%6,%7}, {%8,%9}, {%0,%1,%2,%3};"
                        : "+f"(acc[mt][nt][0]), "+f"(acc[mt][nt][1]),
                          "+f"(acc[mt][nt][2]), "+f"(acc[mt][nt][3])
                        : "r"(aR[mt][0]), "r"(aR[mt][1]), "r"(aR[mt][2]), "r"(aR[mt][3]),
                          "r"(bR[np][2*hi]), "r"(bR[np][2*hi + 1]));
                }
        }
        if (++st == 3) st = 0;
    }

    // ---- epilogue ----
#pragma unroll
    for (int mt = 0; mt < 2; mt++) {
#pragma unroll
        for (int nt = 0; nt < 8; nt++) {
            int row0 = bm + wm*32 + mt*16 + (lane >> 2);
            int col  = bn + wn*64 + nt*8 + ((lane & 3) << 1);
#pragma unroll
            for (int h = 0; h < 2; h++) {
                int row = row0 + 8*h;
                if (row < Mloc) {
                    float v0 = acc[mt][nt][2*h];
                    float v1 = acc[mt][nt][2*h + 1];
                    if (EPI == EPI_NONE) {
                        *(__nv_bfloat162*)(Cbe + (size_t)row*ldc + col) =
                            __floats2bfloat162_rn(v0, v1);
                        continue;
                    } else if (EPI == EPI_BIAS_GELU) {
                        v0 += be[col];     v1 += be[col + 1];
                        v0 = 0.5f*v0*(1.f + erff(v0*0.7071067811865475f));
                        v1 = 0.5f*v1*(1.f + erff(v1*0.7071067811865475f));
                        *(__nv_bfloat162*)(Me + (size_t)row*ldc + col) =
                            __floats2bfloat162_rn(v0, v1);
                        continue;
                    } else if (EPI == EPI_BIAS) {
                        v0 += be[col];     v1 += be[col + 1];
                    } else if (EPI == EPI_RES) {
                        float2 r2 = *(const float2*)(res + (size_t)row*ldc + col);
                        v0 += r2.x;        v1 += r2.y;
                    }
                    float2 o2; o2.x = v0; o2.y = v1;
                    *(float2*)(Ce + (size_t)row*ldc + col) = o2;
                    if (EPI == EPI_RES)
                        *(__nv_bfloat162*)(Me + (size_t)row*ldc + col) =
                            __floats2bfloat162_rn(v0, v1);
                }
            }
        }
    }
}

// ---------------- bf16 tensor-core wave attention: one block per (b, head) ----------
#define AQROWB 80
#define APROWB 272
#define AOFF_K 10240
#define AOFF_V 20480
#define AOFF_P 30720
#define AOFF_W 65536
#define AOFF_R 66048
#define ATT_SMEM (AOFF_R + 1024)

__global__ __launch_bounds__(256)
void attn_bf(const __nv_bfloat16* __restrict__ q, const __nv_bfloat16* __restrict__ k,
             const __nv_bfloat16* __restrict__ v, const float* __restrict__ wfreq,
             const float* __restrict__ wphase, __nv_bfloat16* __restrict__ out, int layer) {
    extern __shared__ char smc[];
    __nv_bfloat16* Qs = (__nv_bfloat16*)smc;
    __nv_bfloat16* Ks = (__nv_bfloat16*)(smc + AOFF_K);
    __nv_bfloat16* Vs = (__nv_bfloat16*)(smc + AOFF_V);
    __nv_bfloat16* Ps = (__nv_bfloat16*)(smc + AOFF_P);
    float* wav = (float*)(smc + AOFF_W);
    float* red = (float*)(smc + AOFF_R);

    int b = blockIdx.x >> 3, hh = blockIdx.x & 7;
    int tid = threadIdx.x, lane = tid & 31, wid = tid >> 5;
    int wm = wid & 3, wn = wid >> 2;

    if (tid < L_) {
        float fr = wfreq[layer*H_ + hh], ph = wphase[layer*H_ + hh];
        wav[tid] = cosf(6.283185307179586f*fr*(float)tid + ph) * 0.17677669529663688f;
    }

#pragma unroll
    for (int p = 0; p < 2; p++) {
        int f = tid + p*256;
        int r = f >> 2, q4 = f & 3;
        size_t gsrc = (size_t)(b*L_ + r)*D_ + hh*DK_ + q4*8;
        int dst = r*40 + q4*8;
        *(uint4*)(Qs + dst) = *(const uint4*)(q + gsrc);
        *(uint4*)(Ks + dst) = *(const uint4*)(k + gsrc);
        *(uint4*)(Vs + dst) = *(const uint4*)(v + gsrc);
    }
    __syncthreads();

    float acc[2][8][4];
#pragma unroll
    for (int mt = 0; mt < 2; mt++)
#pragma unroll
        for (int nt = 0; nt < 8; nt++)
#pragma unroll
            for (int i = 0; i < 4; i++) acc[mt][nt][i] = 0.f;
    {
        uint32_t aB = smem_u32(Qs) + (uint32_t)((wm*32 + (lane & 7) + 8*((lane >> 3) & 1))*AQROWB
                                                + 16*(lane >> 4));
        uint32_t bB = smem_u32(Ks) + (uint32_t)((wn*64 + (lane & 7) + 8*(lane >> 4))*AQROWB
                                                + 16*((lane >> 3) & 1));
#pragma unroll
        for (int s = 0; s < 2; s++) {
            uint32_t aR[2][4];
#pragma unroll
            for (int mt = 0; mt < 2; mt++) {
                uint32_t addr = aB + (uint32_t)(mt*16*AQROWB + s*32);
                asm volatile("ldmatrix.sync.aligned.m8n8.x4.shared.b16 {%0,%1,%2,%3}, [%4];"
                    : "=r"(aR[mt][0]), "=r"(aR[mt][1]), "=r"(aR[mt][2]), "=r"(aR[mt][3])
                    : "r"(addr));
            }
            uint32_t bR[4][4];
#pragma unroll
            for (int np = 0; np < 4; np++) {
                uint32_t addr = bB + (uint32_t)(np*16*AQROWB + s*32);
                asm volatile("ldmatrix.sync.aligned.m8n8.x4.shared.b16 {%0,%1,%2,%3}, [%4];"
                    : "=r"(bR[np][0]), "=r"(bR[np][1]), "=r"(bR[np][2]), "=r"(bR[np][3])
                    : "r"(addr));
            }
#pragma unroll
            for (int mt = 0; mt < 2; mt++)
#pragma unroll
                for (int nt = 0; nt < 8; nt++) {
                    int np = nt >> 1, hi = nt & 1;
                    asm volatile(
                        "mma.sync.aligned.m16n8k16.row.col.f32.bf16.bf16.f32 "
                        "{%0,%1,%2,%3}, {%4,%5,%6,%7}, {%8,%9}, {%0,%1,%2,%3};"
                        : "+f"(acc[mt][nt][0]), "+f"(acc[mt][nt][1]),
                          "+f"(acc[mt][nt][2]), "+f"(acc[mt][nt][3])
                        : "r"(aR[mt][0]), "r"(aR[mt][1]), "r"(aR[mt][2]), "r"(aR[mt][3]),
                          "r"(bR[np][2*hi]), "r"(bR[np][2*hi + 1]));
                }
        }
    }

    float rmax[2][2] = {{-1e30f, -1e30f}, {-1e30f, -1e30f}};
#pragma unroll
    for (int mt = 0; mt < 2; mt++)
#pragma unroll
        for (int nt = 0; nt < 8; nt++)
#pragma unroll
            for (int i = 0; i < 4; i++) {
                int col = wn*64 + nt*8 + ((lane & 3) << 1) + (i & 1);
                float s = acc[mt][nt][i] * wav[col];
                acc[mt][nt][i] = s;
                rmax[mt][i >> 1] = fmaxf(rmax[mt][i >> 1], s);
            }
#pragma unroll
    for (int mt = 0; mt < 2; mt++)
#pragma unroll
        for (int h2 = 0; h2 < 2; h2++) {
            float m = rmax[mt][h2];
            m = fmaxf(m, __shfl_xor_sync(0xffffffffu, m, 1));
            m = fmaxf(m, __shfl_xor_sync(0xffffffffu, m, 2));
            rmax[mt][h2] = m;
        }
    if ((lane & 3) == 0) {
#pragma unroll
        for (int mt = 0; mt < 2; mt++)
#pragma unroll
            for (int h2 = 0; h2 < 2; h2++) {
                int row = wm*32 + mt*16 + (lane >> 2) + 8*h2;
                red[row*2 + wn] = rmax[mt][h2];
            }
    }
    __syncthreads();
    float rm[2][2];
#pragma unroll
    for (int mt = 0; mt < 2; mt++)
#pragma unroll
        for (int h2 = 0; h2 < 2; h2++) {
            int row = wm*32 + mt*16 + (lane >> 2) + 8*h2;
            rm[mt][h2] = fmaxf(red[row*2], red[row*2 + 1]);
        }

    float rsum[2][2] = {{0.f, 0.f}, {0.f, 0.f}};
#pragma unroll
    for (int mt = 0; mt < 2; mt++)
#pragma unroll
        for (int nt = 0; nt < 8; nt++)
#pragma unroll
            for (int i = 0; i < 4; i++) {
                float ev = __expf(acc[mt][nt][i] - rm[mt][i >> 1]);
                acc[mt][nt][i] = ev;
                rsum[mt][i >> 1] += ev;
            }
#pragma unroll
    for (int mt = 0; mt < 2; mt++)
#pragma unroll
        for (int h2 = 0; h2 < 2; h2++) {
            float s = rsum[mt][h2];
            s += __shfl_xor_sync(0xffffffffu, s, 1);
            s += __shfl_xor_sync(0xffffffffu, s, 2);
            rsum[mt][h2] = s;
        }
    __syncthreads();
    if ((lane & 3) == 0) {
#pragma unroll
        for (int mt = 0; mt < 2; mt++)
#pragma unroll
            for (int h2 = 0; h2 < 2; h2++) {
                int row = wm*32 + mt*16 + (lane >> 2) + 8*h2;
                red[row*2 + wn] = rsum[mt][h2];
            }
    }
    __syncthreads();
    if (wn == 0 && (lane & 3) == 0) {
#pragma unroll
        for (int mt = 0; mt < 2; mt++)
#pragma unroll
            for (int h2 = 0; h2 < 2; h2++) {
                int row = wm*32 + mt*16 + (lane >> 2) + 8*h2;
                wav[row] = 1.f / (red[row*2] + red[row*2 + 1]);
            }
    }
#pragma unroll
    for (int mt = 0; mt < 2; mt++)
#pragma unroll
        for (int nt = 0; nt < 8; nt++) {
            int row = wm*32 + mt*16 + (lane >> 2);
            int col = wn*64 + nt*8 + ((lane & 3) << 1);
            *(__nv_bfloat162*)(Ps + row*136 + col) =
                __floats2bfloat162_rn(acc[mt][nt][0], acc[mt][nt][1]);
            *(__nv_bfloat162*)(Ps + (row + 8)*136 + col) =
                __floats2bfloat162_rn(acc[mt][nt][2], acc[mt][nt][3]);
        }
    __syncthreads();

    float o[4][4];
#pragma unroll
    for (int nt = 0; nt < 4; nt++)
#pragma unroll
        for (int i = 0; i < 4; i++) o[nt][i] = 0.f;
    {
        uint32_t pB = smem_u32(Ps) + (uint32_t)((wid*16 + (lane & 7) + 8*((lane >> 3) & 1))*APROWB
                                                + 16*(lane >> 4));
        uint32_t vB = smem_u32(Vs) + (uint32_t)(((lane & 7) + 8*((lane >> 3) & 1))*AQROWB
                                                + 16*(lane >> 4));
#pragma unroll
        for (int kk = 0; kk < 8; kk++) {
            uint32_t aR[4];
            asm volatile("ldmatrix.sync.aligned.m8n8.x4.shared.b16 {%0,%1,%2,%3}, [%4];"
                : "=r"(aR[0]), "=r"(aR[1]), "=r"(aR[2]), "=r"(aR[3])
                : "r"(pB + (uint32_t)(kk*32)));
            uint32_t bV[2][4];
#pragma unroll
            for (int g = 0; g < 2; g++) {
                asm volatile("ldmatrix.sync.aligned.m8n8.x4.trans.shared.b16 {%0,%1,%2,%3}, [%4];"
                    : "=r"(bV[g][0]), "=r"(bV[g][1]), "=r"(bV[g][2]), "=r"(bV[g][3])
                    : "r"(vB + (uint32_t)(kk*16*AQROWB + g*32)));
            }
#pragma unroll
            for (int nt = 0; nt < 4; nt++) {
                int g = nt >> 1, nh = nt & 1;
                asm volatile(
                    "mma.sync.aligned.m16n8k16.row.col.f32.bf16.bf16.f32 "
                    "{%0,%1,%2,%3}, {%4,%5,%6,%7}, {%8,%9}, {%0,%1,%2,%3};"
                    : "+f"(o[nt][0]), "+f"(o[nt][1]), "+f"(o[nt][2]), "+f"(o[nt][3])
                    : "r"(aR[0]), "r"(aR[1]), "r"(aR[2]), "r"(aR[3]),
                      "r"(bV[g][2*nh]), "r"(bV[g][2*nh + 1]));
            }
        }
    }

    float is0 = wav[wid*16 + (lane >> 2)];
    float is1 = wav[wid*16 + (lane >> 2) + 8];
#pragma unroll
    for (int nt = 0; nt < 4; nt++) {
        int row = wid*16 + (lane >> 2);
        int col = nt*8 + ((lane & 3) << 1);
        *(__nv_bfloat162*)(out + (size_t)(b*L_ + row)*D_ + hh*DK_ + col) =
            __floats2bfloat162_rn(o[nt][0]*is0, o[nt][1]*is0);
        *(__nv_bfloat162*)(out + (size_t)(b*L_ + row + 8)*D_ + hh*DK_ + col) =
            __floats2bfloat162_rn(o[nt][2]*is1, o[nt][3]*is1);
    }
}

// ---------------- MoE router + bucketing ----------------
__global__ void router_kernel(const float* __restrict__ rtw, const float* __restrict__ rtb) {
    int lane = threadIdx.x & 31;
    int t = blockIdx.x*8 + (threadIdx.x >> 5);
    const float* xr = g_h + (size_t)t*D_;
    float acc[NE_];
#pragma unroll
    for (int e = 0; e < NE_; e++) acc[e] = 0.f;
    for (int d = lane; d < D_; d += 32) {
        float xv = xr[d];
#pragma unroll
        for (int e = 0; e < NE_; e++) acc[e] += xv * rtw[d*NE_ + e];
    }
#pragma unroll
    for (int off = 16; off > 0; off >>= 1)
#pragma unroll
        for (int e = 0; e < NE_; e++) acc[e] += __shfl_down_sync(0xffffffffu, acc[e], off);
    if (lane == 0) {
        float l0 = -1e30f, l1 = -1e30f; int e0 = 0, e1 = 0;
#pragma unroll
        for (int e = 0; e < NE_; e++) {
            float vv = acc[e] + rtb[e];
            if (vv > l0) { l1 = l0; e1 = e0; l0 = vv; e0 = e; }
            else if (vv > l1) { l1 = vv; e1 = e; }
        }
        float ew = expf(l1 - l0);
        float w0 = 1.f/(1.f + ew);
        float w1 = ew/(1.f + ew);
        int p0 = atomicAdd(&g_cnt[e0], 1); g_list[e0*T_ + p0] = t;
        int p1 = atomicAdd(&g_cnt[e1], 1); g_list[e1*T_ + p1] = t;
        g_ebuf[2*t]   = e0; g_pbuf[2*t]   = p0; g_wbuf[2*t]   = w0;
        g_ebuf[2*t+1] = e1; g_pbuf[2*t+1] = p1; g_wbuf[2*t+1] = w1;
    }
}

// ---------------- combine (grid-stride, 64 tokens/block); zeroes g_cnt for next MoE
__global__ void combine_kernel() {
    int d = threadIdx.x;
    if (blockIdx.x == 0 && d < NE_) {
        // safe: all readers of g_cnt (FFN1/FFN2 launches) completed before combine
    }
    int t0 = blockIdx.x * 64;
#pragma unroll 4
    for (int tk = 0; tk < 64; tk++) {
        int t = t0 + tk;
        float v = g_h[(size_t)t*D_ + d];
#pragma unroll
        for (int kk = 0; kk < 2; kk++) {
            int e = g_ebuf[2*t + kk];
            int p = g_pbuf[2*t + kk];
            float w = g_wbuf[2*t + kk];
            v += w * g_eo[((size_t)e*T_ + p)*D_ + d];
        }
        g_h[(size_t)t*D_ + d] = v;
        g_hx[(size_t)t*D_ + d] = __float2bfloat16(v);
    }
    if (blockIdx.x == 0 && d < NE_) g_cnt[d] = 0;   // reset counters for next MoE layer
}

// ---------------- head ----------------
__global__ void head_kernel(const float* __restrict__ ln_g, const float* __restrict__ ln_b,
                            const float* __restrict__ pw, const float* __restrict__ pb,
                            const float* __restrict__ uw, const float* __restrict__ ub,
                            float* __restrict__ out) {
    __shared__ float red[256];
    __shared__ float norm[256];
    int b = blockIdx.x, d = threadIdx.x;
    float hv = g_h[(size_t)(b*L_ + L_ - 1)*D_ + d];
    red[d] = hv; __syncthreads();
    for (int s = 128; s > 0; s >>= 1) { if (d < s) red[d] += red[d+s]; __syncthreads(); }
    float mu = red[0] * (1.f/256.f);
    __syncthreads();
    float df = hv - mu;
    red[d] = df*df; __syncthreads();
    for (int s = 128; s > 0; s >>= 1) { if (d < s) red[d] += red[d+s]; __syncthreads(); }
    float var = red[0] * (1.f/256.f);
    norm[d] = df * rsqrtf(var + 1e-5f) * ln_g[d] + ln_b[d];
    __syncthreads();
    if (d < 2*NOUT_) {
        int o = d % NOUT_;
        bool un = (d >= NOUT_);
        const float* W = un ? uw : pw;
        float acc = un ? ub[o] : pb[o];
        for (int i = 0; i < D_; i++) acc += norm[i]*W[i*NOUT_ + o];
        if (!un) out[b*NOUT_ + o] = acc;
        else     out[B_*NOUT_ + b*NOUT_ + o] = (acc > 20.f) ? acc : log1pf(expf(acc));
    }
}

// ---------------- launch ----------------
extern "C" void kernel_launch(void* const* d_in, const int* in_sizes, int n_in,
                              void* d_out, int out_size) {
    const float* x     = (const float*)d_in[0];
    const float* emb_w = (const float*)d_in[1];
    const float* emb_b = (const float*)d_in[2];
    const float* wq    = (const float*)d_in[3];
    const float* wk    = (const float*)d_in[4];
    const float* wv    = (const float*)d_in[5];
    const float* wo    = (const float*)d_in[6];
    const float* wfreq = (const float*)d_in[7];
    const float* wph   = (const float*)d_in[8];
    const float* rtw   = (const float*)d_in[9];
    const float* rtb   = (const float*)d_in[10];
    const float* ew1   = (const float*)d_in[11];
    const float* eb1   = (const float*)d_in[12];
    const float* ew2   = (const float*)d_in[13];
    const float* eb2   = (const float*)d_in[14];
    const float* ln_g  = (const float*)d_in[15];
    const float* ln_b  = (const float*)d_in[16];
    const float* pw    = (const float*)d_in[17];
    const float* pb    = (const float*)d_in[18];
    const float* uw    = (const float*)d_in[19];
    const float* ub    = (const float*)d_in[20];
    float* out = (float*)d_out;

    float *ph, *peo;
    __nv_bfloat16 *phx, *pqx, *pkx, *pvx, *paox, *phb, *pwta, *pw1t, *pw2t;
    int *pcnt, *plist;
    cudaGetSymbolAddress((void**)&ph,   g_h);
    cudaGetSymbolAddress((void**)&phx,  g_hx);
    cudaGetSymbolAddress((void**)&pqx,  g_qx);
    cudaGetSymbolAddress((void**)&pkx,  g_kx);
    cudaGetSymbolAddress((void**)&pvx,  g_vx);
    cudaGetSymbolAddress((void**)&paox, g_aox);
    cudaGetSymbolAddress((void**)&peo,  g_eo);
    cudaGetSymbolAddress((void**)&phb,  g_hb);
    cudaGetSymbolAddress((void**)&pwta, g_wta);
    cudaGetSymbolAddress((void**)&pw1t, g_w1t);
    cudaGetSymbolAddress((void**)&pw2t, g_w2t);
    cudaGetSymbolAddress((void**)&pcnt, g_cnt);
    cudaGetSymbolAddress((void**)&plist,g_list);

    cudaFuncSetAttribute(attn_bf, cudaFuncAttributeMaxDynamicSharedMemorySize, ATT_SMEM);
    cudaFuncSetAttribute(bf_gemm<EPI_NONE>,      cudaFuncAttributeMaxDynamicSharedMemorySize, GEMM_SMEM);
    cudaFuncSetAttribute(bf_gemm<EPI_RES>,       cudaFuncAttributeMaxDynamicSharedMemorySize, GEMM_SMEM);
    cudaFuncSetAttribute(bf_gemm<EPI_BIAS_GELU>, cudaFuncAttributeMaxDynamicSharedMemorySize, GEMM_SMEM);
    cudaFuncSetAttribute(bf_gemm<EPI_BIAS>,      cudaFuncAttributeMaxDynamicSharedMemorySize, GEMM_SMEM);

    // ---- pre-transpose weights to bf16 [n][k] ----
    transpose_attnw<<<dim3(8, 8, 4*NL_), 256>>>(wq, wk, wv, wo, pwta);
    transpose_w<<<dim3(8, 32, NMOE_*NE_), 256>>>(ew1, pw1t, D_, DFF_, (size_t)D_*DFF_, 0, (size_t)D_*DFF_);
    transpose_w<<<dim3(32, 8, NMOE_*NE_), 256>>>(ew2, pw2t, DFF_, D_, (size_t)D_*DFF_, 0, (size_t)D_*DFF_);

    embed_kernel<<<T_/128, D_>>>(x, emb_w, emb_b);   // also zeroes g_cnt

    for (int i = 0; i < NL_; i++) {
        const __nv_bfloat16* wtl = pwta + (size_t)i*4*D_*D_;

        // fused QKV (bf16 outputs): z selects W and C
        dim3 gqkv(T_/128, D_/128, 3);
        bf_gemm<EPI_NONE><<<gqkv, 256, GEMM_SMEM>>>(
            phx, D_, 0, wtl, (size_t)D_*D_,
            nullptr, pqx, pkx, pvx, D_, 0,
            nullptr, 0, nullptr, 0, nullptr, nullptr, 0, nullptr,
            T_, D_, D_, 1);

        attn_bf<<<B_*H_, 256, ATT_SMEM>>>(pqx, pkx, pvx, wfreq, wph, paox, i);

        dim3 gproj(T_/128, D_/128, 1);
        bf_gemm<EPI_RES><<<gproj, 256, GEMM_SMEM>>>(
            paox, D_, 0, wtl + (size_t)3*D_*D_, 0,
            ph, nullptr, nullptr, nullptr, D_, 0,
            phx, 0, nullptr, 0, ph, nullptr, 0, nullptr,
            T_, D_, D_, 0);

        if (i % 2 == 0) {
            int m = i / 2;
            router_kernel<<<T_/8, 256>>>(rtw + (size_t)m*D_*NE_, rtb + m*NE_);

            // FFN1: hb(bf16) = gelu(x @ w1 + b1), gathered rows of g_hx
            dim3 g1(T_/128, DFF_/128, NE_);
            bf_gemm<EPI_BIAS_GELU><<<g1, 256, GEMM_SMEM>>>(
                phx, D_, 0,
                pw1t + (size_t)m*NE_*D_*DFF_, (size_t)D_*DFF_,
                nullptr, nullptr, nullptr, nullptr, DFF_, 0,
                phb, (size_t)T_*DFF_,
                eb1 + (size_t)m*NE_*DFF_, DFF_,
                nullptr,
                plist, T_, pcnt,
                T_, DFF_, D_, 0);

            // FFN2: eo = hb @ w2 + b2
            dim3 g2(T_/128, D_/128, NE_);
            bf_gemm<EPI_BIAS><<<g2, 256, GEMM_SMEM>>>(
                phb, DFF_, (size_t)T_*DFF_,
                pw2t + (size_t)m*NE_*D_*DFF_, (size_t)D_*DFF_,
                peo, nullptr, nullptr, nullptr, D_, (size_t)T_*D_,
                nullptr, 0,
                eb2 + (size_t)m*NE_*D_, D_,
                nullptr,
                nullptr, 0, pcnt,
                T_, D_, DFF_, 0);

            combine_kernel<<<T_/64, D_>>>();   // also zeroes g_cnt for next MoE layer
        }
    }
    head_kernel<<<B_, D_>>>(ln_g, ln_b, pw, pb, uw, ub, out);
}

// round 15
// speedup vs baseline: 1.0444x; 1.0444x over previous
#include <cuda_runtime.h>
#include <cuda_bf16.h>
#include <math.h>
#include <stdint.h>

#define B_ 128
#define L_ 128
#define T_ (B_*L_)
#define DIN_ 6
#define D_ 256
#define H_ 8
#define DK_ 32
#define NL_ 6
#define NE_ 8
#define NMOE_ 3
#define DFF_ 1024
#define NOUT_ 5

// ---------------- device scratch (no allocations allowed) ----------------
__device__ float g_h[T_*D_];                         // fp32 residual stream
__device__ __nv_bfloat16 g_hx[T_*D_];                // bf16 mirror of g_h
__device__ __nv_bfloat16 g_qx[T_*D_];
__device__ __nv_bfloat16 g_kx[T_*D_];
__device__ __nv_bfloat16 g_vx[T_*D_];
__device__ __nv_bfloat16 g_aox[T_*D_];               // attention output (bf16)
__device__ float g_eo[(size_t)NE_*T_*D_];            // expert outputs (fp32)
__device__ __nv_bfloat16 g_hb[(size_t)NE_*T_*DFF_];  // FFN hidden (bf16)
__device__ int   g_cnt[NE_];
__device__ int   g_list[NE_*T_];
__device__ int   g_ebuf[T_*2];
__device__ int   g_pbuf[T_*2];
__device__ float g_wbuf[T_*2];
// pre-transposed bf16 weights, K-major [n][k]
__device__ __nv_bfloat16 g_wta[NL_*4*D_*D_];               // [layer][q,k,v,o][n][k]
__device__ __nv_bfloat16 g_w1t[(size_t)NMOE_*NE_*DFF_*D_]; // [m][e][dff][d]
__device__ __nv_bfloat16 g_w2t[(size_t)NMOE_*NE_*D_*DFF_]; // [m][e][d][dff]

__device__ __forceinline__ uint32_t smem_u32(const void* p) {
    uint32_t a;
    asm("{ .reg .u64 t; cvta.to.shared.u64 t, %1; cvt.u32.u64 %0, t; }" : "=r"(a) : "l"(p));
    return a;
}

// ---------------- weight transpose: fp32 [K][N] -> bf16 [N][K] ----------------
__global__ void transpose_w(const float* __restrict__ src, __nv_bfloat16* __restrict__ dst,
                            int K, int N, size_t srcStride, size_t dstOff, size_t dstStride) {
    __shared__ float tile[32][33];
    int z = blockIdx.z;
    const float* sm_ = src + (size_t)z*srcStride;
    __nv_bfloat16* dm = dst + dstOff + (size_t)z*dstStride;
    int k0 = blockIdx.x*32, n0 = blockIdx.y*32;
    int tid = threadIdx.x;
#pragma unroll
    for (int i = 0; i < 4; i++) {
        int f = tid + i*256;
        int kk = f >> 5, nn = f & 31;
        tile[kk][nn] = sm_[(size_t)(k0 + kk)*N + n0 + nn];
    }
    __syncthreads();
#pragma unroll
    for (int i = 0; i < 2; i++) {
        int f = tid + i*256;
        int r = f >> 4, c = f & 15;
        __nv_bfloat162 v = __floats2bfloat162_rn(tile[2*c][r], tile[2*c + 1][r]);
        *(__nv_bfloat162*)(dm + (size_t)(n0 + r)*K + k0 + 2*c) = v;
    }
}

// fused attention-weight transpose: z = layer*4 + {q,k,v,o}
__global__ void transpose_attnw(const float* __restrict__ wq, const float* __restrict__ wk,
                                const float* __restrict__ wv, const float* __restrict__ wo,
                                __nv_bfloat16* __restrict__ dst) {
    __shared__ float tile[32][33];
    int z = blockIdx.z;
    int layer = z >> 2, widx = z & 3;
    const float* srcs[4] = {wq, wk, wv, wo};
    const float* sm_ = srcs[widx] + (size_t)layer*D_*D_;
    __nv_bfloat16* dm = dst + (size_t)z*D_*D_;
    int k0 = blockIdx.x*32, n0 = blockIdx.y*32;
    int tid = threadIdx.x;
#pragma unroll
    for (int i = 0; i < 4; i++) {
        int f = tid + i*256;
        int kk = f >> 5, nn = f & 31;
        tile[kk][nn] = sm_[(size_t)(k0 + kk)*D_ + n0 + nn];
    }
    __syncthreads();
#pragma unroll
    for (int i = 0; i < 2; i++) {
        int f = tid + i*256;
        int r = f >> 4, c = f & 15;
        __nv_bfloat162 v = __floats2bfloat162_rn(tile[2*c][r], tile[2*c + 1][r]);
        *(__nv_bfloat162*)(dm + (size_t)(n0 + r)*D_ + k0 + 2*c) = v;
    }
}

// ---------------- embed: 128 tokens/block, x staged in smem, w in registers --------
__global__ void embed_kernel(const float* __restrict__ x,
                             const float* __restrict__ w,
                             const float* __restrict__ b) {
    __shared__ float xs[128*DIN_];
    int d = threadIdx.x;
    int t0 = blockIdx.x * 128;
    if (blockIdx.x == 0 && d < NE_) g_cnt[d] = 0;     // zero MoE counters for layer 0
#pragma unroll
    for (int i = 0; i < 3; i++) xs[d + i*256] = x[(size_t)t0*DIN_ + d + i*256];
    float wr[DIN_];
#pragma unroll
    for (int i = 0; i < DIN_; i++) wr[i] = w[i*D_ + d];
    float bb = b[d];
    __syncthreads();
#pragma unroll 4
    for (int tk = 0; tk < 128; tk++) {
        float acc = bb;
#pragma unroll
        for (int i = 0; i < DIN_; i++) acc += xs[tk*DIN_ + i] * wr[i];
        g_h[(size_t)(t0 + tk)*D_ + d] = acc;
        g_hx[(size_t)(t0 + tk)*D_ + d] = __float2bfloat16(acc);
    }
}

// ---------------- bf16 tensor-core GEMM, 3-stage cp.async (8B), 1 barrier/chunk ----
#define EPI_NONE      0
#define EPI_RES       1
#define EPI_BIAS_GELU 2
#define EPI_BIAS      3

#define KROW 20
#define STG_U32 (128*KROW)                 // 2560 u32 = 10240 B per operand stage
#define GEMM_SMEM (6*STG_U32*4)            // 61440 B (A0..A2, B0..B2)

template<int EPI>
__global__ __launch_bounds__(256, 2)
void bf_gemm(const __nv_bfloat16* __restrict__ A, int lda, size_t strideA,
             const __nv_bfloat16* __restrict__ Wt, size_t strideW,
             float* __restrict__ C, __nv_bfloat16* __restrict__ Cb,
             __nv_bfloat16* __restrict__ Cb2, __nv_bfloat16* __restrict__ Cb3,
             int ldc, size_t strideC,
             __nv_bfloat16* __restrict__ mirror, size_t strideMir,
             const float* __restrict__ bias, size_t strideBias,
             const float* __restrict__ res,
             const int* __restrict__ gather, size_t strideGather,
             const int* __restrict__ cntPtr,
             int M, int N, int K, int qkv) {
    extern __shared__ float smf[];
    uint32_t smem_base = smem_u32(smf);

    int e = blockIdx.z;
    const __nv_bfloat16* Ae = A;
    const __nv_bfloat16* We = Wt + (size_t)e*strideW;
    float* Ce = nullptr;
    __nv_bfloat16* Cbe = nullptr;
    __nv_bfloat16* Me = nullptr;
    const float* be = nullptr;
    const int* ge = nullptr;
    int Mloc = M;
    if (qkv) {
        Cbe = (e == 0) ? Cb : (e == 1) ? Cb2 : Cb3;
    } else {
        Ae = A + (size_t)e*strideA;
        if (C) Ce = C + (size_t)e*strideC;
        if (mirror) Me = mirror + (size_t)e*strideMir;
        if (bias)   be = bias + (size_t)e*strideBias;
        if (gather) ge = gather + (size_t)e*strideGather;
        if (cntPtr) Mloc = cntPtr[e];
    }

    int bm = blockIdx.x * 128;
    if (bm >= Mloc) return;
    int bn = blockIdx.y * 128;

    int tid = threadIdx.x;
    int lane = tid & 31;
    int wid = tid >> 5;
    int wm = wid & 3;        // tok direction (4 x 32)
    int wn = wid >> 2;       // n direction  (2 x 64)

    // ---- per-thread cp.async descriptors (8B ops, 4 per operand) ----
    const __nv_bfloat16* asrc[4]; int apred[4]; uint32_t adst[4];
    const __nv_bfloat16* bsrc[4]; uint32_t bdst[4];
#pragma unroll
    for (int p = 0; p < 4; p++) {
        int f = tid + p*256;
        int r = f >> 3, q = f & 7;               // row, 8B-chunk (4 bf16)
        int grow = bm + r;
        apred[p] = (grow < Mloc) ? 8 : 0;
        int gc = (grow < Mloc) ? grow : 0;
        int arow = ge ? ge[gc] : gc;
        asrc[p] = Ae + (size_t)arow*lda + q*4;
        adst[p] = (uint32_t)((r*KROW + q*2)*4);
        bsrc[p] = We + (size_t)(bn + r)*K + q*4;
        bdst[p] = (uint32_t)((r*KROW + q*2)*4);
    }

    auto load_chunk = [&](int st, int ki) {
        int k0 = ki << 5;
        uint32_t aBase = smem_base + (uint32_t)(st*STG_U32*4);
        uint32_t bBase = smem_base + (uint32_t)((3 + st)*STG_U32*4);
#pragma unroll
        for (int p = 0; p < 4; p++)
            asm volatile("cp.async.ca.shared.global [%0], [%1], 8, %2;"
                         :: "r"(aBase + adst[p]), "l"(asrc[p] + k0), "r"(apred[p]));
#pragma unroll
        for (int p = 0; p < 4; p++)
            asm volatile("cp.async.ca.shared.global [%0], [%1], 8;"
                         :: "r"(bBase + bdst[p]), "l"(bsrc[p] + k0));
        asm volatile("cp.async.commit_group;");
    };

    uint32_t aLdm = (uint32_t)(((wm*32 + (lane & 7) + 8*((lane >> 3) & 1))*KROW
                                + 4*(lane >> 4))*4);
    uint32_t bLdm = (uint32_t)(((wn*64 + (lane & 7) + 8*(lane >> 4))*KROW
                                + 4*((lane >> 3) & 1))*4);

    float acc[2][8][4];
#pragma unroll
    for (int mt = 0; mt < 2; mt++)
#pragma unroll
        for (int nt = 0; nt < 8; nt++)
#pragma unroll
            for (int i = 0; i < 4; i++) acc[mt][nt][i] = 0.f;

    int nk = K >> 5;
    load_chunk(0, 0);
    if (nk > 1) load_chunk(1, 1);

    int st = 0;
    for (int ki = 0; ki < nk; ki++) {
        if (ki + 1 < nk) asm volatile("cp.async.wait_group 1;");
        else             asm volatile("cp.async.wait_group 0;");
        __syncthreads();
        if (ki + 2 < nk) {
            int s2 = st + 2; if (s2 >= 3) s2 -= 3;
            load_chunk(s2, ki + 2);
        }

        uint32_t aB = smem_base + (uint32_t)(st*STG_U32*4) + aLdm;
        uint32_t bB = smem_base + (uint32_t)((3 + st)*STG_U32*4) + bLdm;
#pragma unroll
        for (int s = 0; s < 2; s++) {
            uint32_t aR[2][4];
#pragma unroll
            for (int mt = 0; mt < 2; mt++) {
                uint32_t addr = aB + (uint32_t)(mt*16*KROW*4 + s*32);
                asm volatile("ldmatrix.sync.aligned.m8n8.x4.shared.b16 {%0,%1,%2,%3}, [%4];"
                    : "=r"(aR[mt][0]), "=r"(aR[mt][1]), "=r"(aR[mt][2]), "=r"(aR[mt][3])
                    : "r"(addr));
            }
            uint32_t bR[4][4];
#pragma unroll
            for (int np = 0; np < 4; np++) {
                uint32_t addr = bB + (uint32_t)(np*16*KROW*4 + s*32);
                asm volatile("ldmatrix.sync.aligned.m8n8.x4.shared.b16 {%0,%1,%2,%3}, [%4];"
                    : "=r"(bR[np][0]), "=r"(bR[np][1]), "=r"(bR[np][2]), "=r"(bR[np][3])
                    : "r"(addr));
            }
#pragma unroll
            for (int mt = 0; mt < 2; mt++)
#pragma unroll
                for (int nt = 0; nt < 8; nt++) {
                    int np = nt >> 1, hi = nt & 1;
                    asm volatile(
                        "mma.sync.aligned.m16n8k16.row.col.f32.bf16.bf16.f32 "
                        "{%0,%1,%2,%3}, {%4,%5,%6,%7}, {%8,%9}, {%0,%1,%2,%3};"
                        : "+f"(acc[mt][nt][0]), "+f"(acc[mt][nt][1]),
                          "+f"(acc[mt][nt][2]), "+f"(acc[mt][nt][3])
                        : "r"(aR[mt][0]), "r"(aR[mt][1]), "r"(aR[mt][2]), "r"(aR[mt][3]),
                          "r"(bR[np][2*hi]), "r"(bR[np][2*hi + 1]));
                }
        }
        if (++st == 3) st = 0;
    }

    // ---- epilogue ----
#pragma unroll
    for (int mt = 0; mt < 2; mt++) {
#pragma unroll
        for (int nt = 0; nt < 8; nt++) {
            int row0 = bm + wm*32 + mt*16 + (lane >> 2);
            int col  = bn + wn*64 + nt*8 + ((lane & 3) << 1);
#pragma unroll
            for (int h = 0; h < 2; h++) {
                int row = row0 + 8*h;
                if (row < Mloc) {
                    float v0 = acc[mt][nt][2*h];
                    float v1 = acc[mt][nt][2*h + 1];
                    if (EPI == EPI_NONE) {
                        *(__nv_bfloat162*)(Cbe + (size_t)row*ldc + col) =
                            __floats2bfloat162_rn(v0, v1);
                        continue;
                    } else if (EPI == EPI_BIAS_GELU) {
                        v0 += be[col];     v1 += be[col + 1];
                        v0 = 0.5f*v0*(1.f + erff(v0*0.7071067811865475f));
                        v1 = 0.5f*v1*(1.f + erff(v1*0.7071067811865475f));
                        *(__nv_bfloat162*)(Me + (size_t)row*ldc + col) =
                            __floats2bfloat162_rn(v0, v1);
                        continue;
                    } else if (EPI == EPI_BIAS) {
                        v0 += be[col];     v1 += be[col + 1];
                    } else if (EPI == EPI_RES) {
                        float2 r2 = *(const float2*)(res + (size_t)row*ldc + col);
                        v0 += r2.x;        v1 += r2.y;
                    }
                    float2 o2; o2.x = v0; o2.y = v1;
                    *(float2*)(Ce + (size_t)row*ldc + col) = o2;
                    if (EPI == EPI_RES)
                        *(__nv_bfloat162*)(Me + (size_t)row*ldc + col) =
                            __floats2bfloat162_rn(v0, v1);
                }
            }
        }
    }
}

// ---------------- bf16 tensor-core wave attention: one block per (b, head) ----------
#define AQROWB 80
#define APROWB 272
#define AOFF_K 10240
#define AOFF_V 20480
#define AOFF_P 30720
#define AOFF_W 65536
#define AOFF_R 66048
#define ATT_SMEM (AOFF_R + 1024)

__global__ __launch_bounds__(256)
void attn_bf(const __nv_bfloat16* __restrict__ q, const __nv_bfloat16* __restrict__ k,
             const __nv_bfloat16* __restrict__ v, const float* __restrict__ wfreq,
             const float* __restrict__ wphase, __nv_bfloat16* __restrict__ out, int layer) {
    extern __shared__ char smc[];
    __nv_bfloat16* Qs = (__nv_bfloat16*)smc;
    __nv_bfloat16* Ks = (__nv_bfloat16*)(smc + AOFF_K);
    __nv_bfloat16* Vs = (__nv_bfloat16*)(smc + AOFF_V);
    __nv_bfloat16* Ps = (__nv_bfloat16*)(smc + AOFF_P);
    float* wav = (float*)(smc + AOFF_W);
    float* red = (float*)(smc + AOFF_R);

    int b = blockIdx.x >> 3, hh = blockIdx.x & 7;
    int tid = threadIdx.x, lane = tid & 31, wid = tid >> 5;
    int wm = wid & 3, wn = wid >> 2;

    if (tid < L_) {
        float fr = wfreq[layer*H_ + hh], ph = wphase[layer*H_ + hh];
        wav[tid] = cosf(6.283185307179586f*fr*(float)tid + ph) * 0.17677669529663688f;
    }

#pragma unroll
    for (int p = 0; p < 2; p++) {
        int f = tid + p*256;
        int r = f >> 2, q4 = f & 3;
        size_t gsrc = (size_t)(b*L_ + r)*D_ + hh*DK_ + q4*8;
        int dst = r*40 + q4*8;
        *(uint4*)(Qs + dst) = *(const uint4*)(q + gsrc);
        *(uint4*)(Ks + dst) = *(const uint4*)(k + gsrc);
        *(uint4*)(Vs + dst) = *(const uint4*)(v + gsrc);
    }
    __syncthreads();

    float acc[2][8][4];
#pragma unroll
    for (int mt = 0; mt < 2; mt++)
#pragma unroll
        for (int nt = 0; nt < 8; nt++)
#pragma unroll
            for (int i = 0; i < 4; i++) acc[mt][nt][i] = 0.f;
    {
        uint32_t aB = smem_u32(Qs) + (uint32_t)((wm*32 + (lane & 7) + 8*((lane >> 3) & 1))*AQROWB
                                                + 16*(lane >> 4));
        uint32_t bB = smem_u32(Ks) + (uint32_t)((wn*64 + (lane & 7) + 8*(lane >> 4))*AQROWB
                                                + 16*((lane >> 3) & 1));
#pragma unroll
        for (int s = 0; s < 2; s++) {
            uint32_t aR[2][4];
#pragma unroll
            for (int mt = 0; mt < 2; mt++) {
                uint32_t addr = aB + (uint32_t)(mt*16*AQROWB + s*32);
                asm volatile("ldmatrix.sync.aligned.m8n8.x4.shared.b16 {%0,%1,%2,%3}, [%4];"
                    : "=r"(aR[mt][0]), "=r"(aR[mt][1]), "=r"(aR[mt][2]), "=r"(aR[mt][3])
                    : "r"(addr));
            }
            uint32_t bR[4][4];
#pragma unroll
            for (int np = 0; np < 4; np++) {
                uint32_t addr = bB + (uint32_t)(np*16*AQROWB + s*32);
                asm volatile("ldmatrix.sync.aligned.m8n8.x4.shared.b16 {%0,%1,%2,%3}, [%4];"
                    : "=r"(bR[np][0]), "=r"(bR[np][1]), "=r"(bR[np][2]), "=r"(bR[np][3])
                    : "r"(addr));
            }
#pragma unroll
            for (int mt = 0; mt < 2; mt++)
#pragma unroll
                for (int nt = 0; nt < 8; nt++) {
                    int np = nt >> 1, hi = nt & 1;
                    asm volatile(
                        "mma.sync.aligned.m16n8k16.row.col.f32.bf16.bf16.f32 "
                        "{%0,%1,%2,%3}, {%4,%5,%6,%7}, {%8,%9}, {%0,%1,%2,%3};"
                        : "+f"(acc[mt][nt][0]), "+f"(acc[mt][nt][1]),
                          "+f"(acc[mt][nt][2]), "+f"(acc[mt][nt][3])
                        : "r"(aR[mt][0]), "r"(aR[mt][1]), "r"(aR[mt][2]), "r"(aR[mt][3]),
                          "r"(bR[np][2*hi]), "r"(bR[np][2*hi + 1]));
                }
        }
    }

    float rmax[2][2] = {{-1e30f, -1e30f}, {-1e30f, -1e30f}};
#pragma unroll
    for (int mt = 0; mt < 2; mt++)
#pragma unroll
        for (int nt = 0; nt < 8; nt++)
#pragma unroll
            for (int i = 0; i < 4; i++) {
                int col = wn*64 + nt*8 + ((lane & 3) << 1) + (i & 1);
                float s = acc[mt][nt][i] * wav[col];
                acc[mt][nt][i] = s;
                rmax[mt][i >> 1] = fmaxf(rmax[mt][i >> 1], s);
            }
#pragma unroll
    for (int mt = 0; mt < 2; mt++)
#pragma unroll
        for (int h2 = 0; h2 < 2; h2++) {
            float m = rmax[mt][h2];
            m = fmaxf(m, __shfl_xor_sync(0xffffffffu, m, 1));
            m = fmaxf(m, __shfl_xor_sync(0xffffffffu, m, 2));
            rmax[mt][h2] = m;
        }
    if ((lane & 3) == 0) {
#pragma unroll
        for (int mt = 0; mt < 2; mt++)
#pragma unroll
            for (int h2 = 0; h2 < 2; h2++) {
                int row = wm*32 + mt*16 + (lane >> 2) + 8*h2;
                red[row*2 + wn] = rmax[mt][h2];
            }
    }
    __syncthreads();
    float rm[2][2];
#pragma unroll
    for (int mt = 0; mt < 2; mt++)
#pragma unroll
        for (int h2 = 0; h2 < 2; h2++) {
            int row = wm*32 + mt*16 + (lane >> 2) + 8*h2;
            rm[mt][h2] = fmaxf(red[row*2], red[row*2 + 1]);
        }

    float rsum[2][2] = {{0.f, 0.f}, {0.f, 0.f}};
#pragma unroll
    for (int mt = 0; mt < 2; mt++)
#pragma unroll
        for (int nt = 0; nt < 8; nt++)
#pragma unroll
            for (int i = 0; i < 4; i++) {
                float ev = __expf(acc[mt][nt][i] - rm[mt][i >> 1]);
                acc[mt][nt][i] = ev;
                rsum[mt][i >> 1] += ev;
            }
#pragma unroll
    for (int mt = 0; mt < 2; mt++)
#pragma unroll
        for (int h2 = 0; h2 < 2; h2++) {
            float s = rsum[mt][h2];
            s += __shfl_xor_sync(0xffffffffu, s, 1);
            s += __shfl_xor_sync(0xffffffffu, s, 2);
            rsum[mt][h2] = s;
        }
    __syncthreads();
    if ((lane & 3) == 0) {
#pragma unroll
        for (int mt = 0; mt < 2; mt++)
#pragma unroll
            for (int h2 = 0; h2 < 2; h2++) {
                int row = wm*32 + mt*16 + (lane >> 2) + 8*h2;
                red[row*2 + wn] = rsum[mt][h2];
            }
    }
    __syncthreads();
    if (wn == 0 && (lane & 3) == 0) {
#pragma unroll
        for (int mt = 0; mt < 2; mt++)
#pragma unroll
            for (int h2 = 0; h2 < 2; h2++) {
                int row = wm*32 + mt*16 + (lane >> 2) + 8*h2;
                wav[row] = 1.f / (red[row*2] + red[row*2 + 1]);
            }
    }
#pragma unroll
    for (int mt = 0; mt < 2; mt++)
#pragma unroll
        for (int nt = 0; nt < 8; nt++) {
            int row = wm*32 + mt*16 + (lane >> 2);
            int col = wn*64 + nt*8 + ((lane & 3) << 1);
            *(__nv_bfloat162*)(Ps + row*136 + col) =
                __floats2bfloat162_rn(acc[mt][nt][0], acc[mt][nt][1]);
            *(__nv_bfloat162*)(Ps + (row + 8)*136 + col) =
                __floats2bfloat162_rn(acc[mt][nt][2], acc[mt][nt][3]);
        }
    __syncthreads();

    float o[4][4];
#pragma unroll
    for (int nt = 0; nt < 4; nt++)
#pragma unroll
        for (int i = 0; i < 4; i++) o[nt][i] = 0.f;
    {
        uint32_t pB = smem_u32(Ps) + (uint32_t)((wid*16 + (lane & 7) + 8*((lane >> 3) & 1))*APROWB
                                                + 16*(lane >> 4));
        uint32_t vB = smem_u32(Vs) + (uint32_t)(((lane & 7) + 8*((lane >> 3) & 1))*AQROWB
                                                + 16*(lane >> 4));
#pragma unroll
        for (int kk = 0; kk < 8; kk++) {
            uint32_t aR[4];
            asm volatile("ldmatrix.sync.aligned.m8n8.x4.shared.b16 {%0,%1,%2,%3}, [%4];"
                : "=r"(aR[0]), "=r"(aR[1]), "=r"(aR[2]), "=r"(aR[3])
                : "r"(pB + (uint32_t)(kk*32)));
            uint32_t bV[2][4];
#pragma unroll
            for (int g = 0; g < 2; g++) {
                asm volatile("ldmatrix.sync.aligned.m8n8.x4.trans.shared.b16 {%0,%1,%2,%3}, [%4];"
                    : "=r"(bV[g][0]), "=r"(bV[g][1]), "=r"(bV[g][2]), "=r"(bV[g][3])
                    : "r"(vB + (uint32_t)(kk*16*AQROWB + g*32)));
            }
#pragma unroll
            for (int nt = 0; nt < 4; nt++) {
                int g = nt >> 1, nh = nt & 1;
                asm volatile(
                    "mma.sync.aligned.m16n8k16.row.col.f32.bf16.bf16.f32 "
                    "{%0,%1,%2,%3}, {%4,%5,%6,%7}, {%8,%9}, {%0,%1,%2,%3};"
                    : "+f"(o[nt][0]), "+f"(o[nt][1]), "+f"(o[nt][2]), "+f"(o[nt][3])
                    : "r"(aR[0]), "r"(aR[1]), "r"(aR[2]), "r"(aR[3]),
                      "r"(bV[g][2*nh]), "r"(bV[g][2*nh + 1]));
            }
        }
    }

    float is0 = wav[wid*16 + (lane >> 2)];
    float is1 = wav[wid*16 + (lane >> 2) + 8];
#pragma unroll
    for (int nt = 0; nt < 4; nt++) {
        int row = wid*16 + (lane >> 2);
        int col = nt*8 + ((lane & 3) << 1);
        *(__nv_bfloat162*)(out + (size_t)(b*L_ + row)*D_ + hh*DK_ + col) =
            __floats2bfloat162_rn(o[nt][0]*is0, o[nt][1]*is0);
        *(__nv_bfloat162*)(out + (size_t)(b*L_ + row + 8)*D_ + hh*DK_ + col) =
            __floats2bfloat162_rn(o[nt][2]*is1, o[nt][3]*is1);
    }
}

// ---------------- MoE router + bucketing ----------------
__global__ void router_kernel(const float* __restrict__ rtw, const float* __restrict__ rtb) {
    int lane = threadIdx.x & 31;
    int t = blockIdx.x*8 + (threadIdx.x >> 5);
    const float* xr = g_h + (size_t)t*D_;
    float acc[NE_];
#pragma unroll
    for (int e = 0; e < NE_; e++) acc[e] = 0.f;
    for (int d = lane; d < D_; d += 32) {
        float xv = xr[d];
#pragma unroll
        for (int e = 0; e < NE_; e++) acc[e] += xv * rtw[d*NE_ + e];
    }
#pragma unroll
    for (int off = 16; off > 0; off >>= 1)
#pragma unroll
        for (int e = 0; e < NE_; e++) acc[e] += __shfl_down_sync(0xffffffffu, acc[e], off);
    if (lane == 0) {
        float l0 = -1e30f, l1 = -1e30f; int e0 = 0, e1 = 0;
#pragma unroll
        for (int e = 0; e < NE_; e++) {
            float vv = acc[e] + rtb[e];
            if (vv > l0) { l1 = l0; e1 = e0; l0 = vv; e0 = e; }
            else if (vv > l1) { l1 = vv; e1 = e; }
        }
        float ew = expf(l1 - l0);
        float w0 = 1.f/(1.f + ew);
        float w1 = ew/(1.f + ew);
        int p0 = atomicAdd(&g_cnt[e0], 1); g_list[e0*T_ + p0] = t;
        int p1 = atomicAdd(&g_cnt[e1], 1); g_list[e1*T_ + p1] = t;
        g_ebuf[2*t]   = e0; g_pbuf[2*t]   = p0; g_wbuf[2*t]   = w0;
        g_ebuf[2*t+1] = e1; g_pbuf[2*t+1] = p1; g_wbuf[2*t+1] = w1;
    }
}

// ---------------- combine (one block per token); zeroes g_cnt for next MoE layer ----
__global__ void combine_kernel() {
    int t = blockIdx.x, d = threadIdx.x;
    float v = g_h[(size_t)t*D_ + d];
#pragma unroll
    for (int kk = 0; kk < 2; kk++) {
        int e = g_ebuf[2*t + kk];
        int p = g_pbuf[2*t + kk];
        float w = g_wbuf[2*t + kk];
        v += w * g_eo[((size_t)e*T_ + p)*D_ + d];
    }
    g_h[(size_t)t*D_ + d] = v;
    g_hx[(size_t)t*D_ + d] = __float2bfloat16(v);
    if (t == 0 && d < NE_) g_cnt[d] = 0;   // reset counters for next MoE layer
}

// ---------------- head ----------------
__global__ void head_kernel(const float* __restrict__ ln_g, const float* __restrict__ ln_b,
                            const float* __restrict__ pw, const float* __restrict__ pb,
                            const float* __restrict__ uw, const float* __restrict__ ub,
                            float* __restrict__ out) {
    __shared__ float red[256];
    __shared__ float norm[256];
    int b = blockIdx.x, d = threadIdx.x;
    float hv = g_h[(size_t)(b*L_ + L_ - 1)*D_ + d];
    red[d] = hv; __syncthreads();
    for (int s = 128; s > 0; s >>= 1) { if (d < s) red[d] += red[d+s]; __syncthreads(); }
    float mu = red[0] * (1.f/256.f);
    __syncthreads();
    float df = hv - mu;
    red[d] = df*df; __syncthreads();
    for (int s = 128; s > 0; s >>= 1) { if (d < s) red[d] += red[d+s]; __syncthreads(); }
    float var = red[0] * (1.f/256.f);
    norm[d] = df * rsqrtf(var + 1e-5f) * ln_g[d] + ln_b[d];
    __syncthreads();
    if (d < 2*NOUT_) {
        int o = d % NOUT_;
        bool un = (d >= NOUT_);
        const float* W = un ? uw : pw;
        float acc = un ? ub[o] : pb[o];
        for (int i = 0; i < D_; i++) acc += norm[i]*W[i*NOUT_ + o];
        if (!un) out[b*NOUT_ + o] = acc;
        else     out[B_*NOUT_ + b*NOUT_ + o] = (acc > 20.f) ? acc : log1pf(expf(acc));
    }
}

// ---------------- launch ----------------
extern "C" void kernel_launch(void* const* d_in, const int* in_sizes, int n_in,
                              void* d_out, int out_size) {
    const float* x     = (const float*)d_in[0];
    const float* emb_w = (const float*)d_in[1];
    const float* emb_b = (const float*)d_in[2];
    const float* wq    = (const float*)d_in[3];
    const float* wk    = (const float*)d_in[4];
    const float* wv    = (const float*)d_in[5];
    const float* wo    = (const float*)d_in[6];
    const float* wfreq = (const float*)d_in[7];
    const float* wph   = (const float*)d_in[8];
    const float* rtw   = (const float*)d_in[9];
    const float* rtb   = (const float*)d_in[10];
    const float* ew1   = (const float*)d_in[11];
    const float* eb1   = (const float*)d_in[12];
    const float* ew2   = (const float*)d_in[13];
    const float* eb2   = (const float*)d_in[14];
    const float* ln_g  = (const float*)d_in[15];
    const float* ln_b  = (const float*)d_in[16];
    const float* pw    = (const float*)d_in[17];
    const float* pb    = (const float*)d_in[18];
    const float* uw    = (const float*)d_in[19];
    const float* ub    = (const float*)d_in[20];
    float* out = (float*)d_out;

    float *ph, *peo;
    __nv_bfloat16 *phx, *pqx, *pkx, *pvx, *paox, *phb, *pwta, *pw1t, *pw2t;
    int *pcnt, *plist;
    cudaGetSymbolAddress((void**)&ph,   g_h);
    cudaGetSymbolAddress((void**)&phx,  g_hx);
    cudaGetSymbolAddress((void**)&pqx,  g_qx);
    cudaGetSymbolAddress((void**)&pkx,  g_kx);
    cudaGetSymbolAddress((void**)&pvx,  g_vx);
    cudaGetSymbolAddress((void**)&paox, g_aox);
    cudaGetSymbolAddress((void**)&peo,  g_eo);
    cudaGetSymbolAddress((void**)&phb,  g_hb);
    cudaGetSymbolAddress((void**)&pwta, g_wta);
    cudaGetSymbolAddress((void**)&pw1t, g_w1t);
    cudaGetSymbolAddress((void**)&pw2t, g_w2t);
    cudaGetSymbolAddress((void**)&pcnt, g_cnt);
    cudaGetSymbolAddress((void**)&plist,g_list);

    cudaFuncSetAttribute(attn_bf, cudaFuncAttributeMaxDynamicSharedMemorySize, ATT_SMEM);
    cudaFuncSetAttribute(bf_gemm<EPI_NONE>,      cudaFuncAttributeMaxDynamicSharedMemorySize, GEMM_SMEM);
    cudaFuncSetAttribute(bf_gemm<EPI_RES>,       cudaFuncAttributeMaxDynamicSharedMemorySize, GEMM_SMEM);
    cudaFuncSetAttribute(bf_gemm<EPI_BIAS_GELU>, cudaFuncAttributeMaxDynamicSharedMemorySize, GEMM_SMEM);
    cudaFuncSetAttribute(bf_gemm<EPI_BIAS>,      cudaFuncAttributeMaxDynamicSharedMemorySize, GEMM_SMEM);

    // ---- pre-transpose weights to bf16 [n][k] ----
    transpose_attnw<<<dim3(8, 8, 4*NL_), 256>>>(wq, wk, wv, wo, pwta);
    transpose_w<<<dim3(8, 32, NMOE_*NE_), 256>>>(ew1, pw1t, D_, DFF_, (size_t)D_*DFF_, 0, (size_t)D_*DFF_);
    transpose_w<<<dim3(32, 8, NMOE_*NE_), 256>>>(ew2, pw2t, DFF_, D_, (size_t)D_*DFF_, 0, (size_t)D_*DFF_);

    embed_kernel<<<T_/128, D_>>>(x, emb_w, emb_b);   // also zeroes g_cnt

    for (int i = 0; i < NL_; i++) {
        const __nv_bfloat16* wtl = pwta + (size_t)i*4*D_*D_;

        // fused QKV (bf16 outputs): z selects W and C
        dim3 gqkv(T_/128, D_/128, 3);
        bf_gemm<EPI_NONE><<<gqkv, 256, GEMM_SMEM>>>(
            phx, D_, 0, wtl, (size_t)D_*D_,
            nullptr, pqx, pkx, pvx, D_, 0,
            nullptr, 0, nullptr, 0, nullptr, nullptr, 0, nullptr,
            T_, D_, D_, 1);

        attn_bf<<<B_*H_, 256, ATT_SMEM>>>(pqx, pkx, pvx, wfreq, wph, paox, i);

        dim3 gproj(T_/128, D_/128, 1);
        bf_gemm<EPI_RES><<<gproj, 256, GEMM_SMEM>>>(
            paox, D_, 0, wtl + (size_t)3*D_*D_, 0,
            ph, nullptr, nullptr, nullptr, D_, 0,
            phx, 0, nullptr, 0, ph, nullptr, 0, nullptr,
            T_, D_, D_, 0);

        if (i % 2 == 0) {
            int m = i / 2;
            router_kernel<<<T_/8, 256>>>(rtw + (size_t)m*D_*NE_, rtb + m*NE_);

            // FFN1: hb(bf16) = gelu(x @ w1 + b1), gathered rows of g_hx
            dim3 g1(T_/128, DFF_/128, NE_);
            bf_gemm<EPI_BIAS_GELU><<<g1, 256, GEMM_SMEM>>>(
                phx, D_, 0,
                pw1t + (size_t)m*NE_*D_*DFF_, (size_t)D_*DFF_,
                nullptr, nullptr, nullptr, nullptr, DFF_, 0,
                phb, (size_t)T_*DFF_,
                eb1 + (size_t)m*NE_*DFF_, DFF_,
                nullptr,
                plist, T_, pcnt,
                T_, DFF_, D_, 0);

            // FFN2: eo = hb @ w2 + b2
            dim3 g2(T_/128, D_/128, NE_);
            bf_gemm<EPI_BIAS><<<g2, 256, GEMM_SMEM>>>(
                phb, DFF_, (size_t)T_*DFF_,
                pw2t + (size_t)m*NE_*D_*DFF_, (size_t)D_*DFF_,
                peo, nullptr, nullptr, nullptr, D_, (size_t)T_*D_,
                nullptr, 0,
                eb2 + (size_t)m*NE_*D_, D_,
                nullptr,
                nullptr, 0, pcnt,
                T_, D_, DFF_, 0);

            combine_kernel<<<T_, D_>>>();   // also zeroes g_cnt for next MoE layer
        }
    }
    head_kernel<<<B_, D_>>>(ln_g, ln_b, pw, pb, uw, ub, out);
}